// round 14
// baseline (speedup 1.0000x reference)
#include <cuda_runtime.h>
#include <cuda_fp16.h>
#include <cstdint>

#define DI __device__ __forceinline__

// ---------------- problem constants (fixed shapes) ----------------
constexpr int NTOK   = 4096;   // B*S = 2*2048
constexpr int DMODEL = 1024;
constexpr int DFF    = 4096;
constexpr int HH     = 32;

// ---------------- scratch (device globals; no allocs allowed) ----------------
__device__ __align__(16) __half g_xh  [NTOK * DMODEL];      // 8 MB
__device__ __align__(16) __half g_w1ah[DFF  * DMODEL];      // 8 MB
__device__ __align__(16) __half g_w1bh[DFF  * DMODEL];      // 8 MB
__device__ __align__(16) __half g_w2h [DMODEL * DFF];       // 8 MB
__device__ __align__(16) __half g_act [(size_t)NTOK * DFF]; // 32 MB
__device__ int g_cnt[NTOK / 128];    // per-m-block gemm1 completion (zeroed each launch)
__device__ int g_w2done;             // W2 conversion progress     (zeroed each launch)

// ---------------- PTX helpers ----------------
DI uint32_t s2u(const void* p) {
    uint32_t a;
    asm("{ .reg .u64 t; cvta.to.shared.u64 t, %1; cvt.u32.u64 %0, t; }"
        : "=r"(a) : "l"(p));
    return a;
}

#define CP_COMMIT() asm volatile("cp.async.commit_group;" ::: "memory")
#define CP_WAIT_1() asm volatile("cp.async.wait_group 1;" ::: "memory")

DI void cp16(uint32_t sdst, const void* gsrc) {
    asm volatile("cp.async.cg.shared.global [%0], [%1], 16;"
                 :: "r"(sdst), "l"(__cvta_generic_to_global(gsrc)) : "memory");
}

DI void ldsm4(uint32_t r[4], uint32_t addr) {
    asm volatile("ldmatrix.sync.aligned.m8n8.x4.shared.b16 {%0,%1,%2,%3}, [%4];"
                 : "=r"(r[0]), "=r"(r[1]), "=r"(r[2]), "=r"(r[3]) : "r"(addr));
}

DI void mma16816(float c[4], const uint32_t a[4], uint32_t b0, uint32_t b1) {
    asm volatile(
        "mma.sync.aligned.m16n8k16.row.col.f32.f16.f16.f32 "
        "{%0,%1,%2,%3}, {%4,%5,%6,%7}, {%8,%9}, {%0,%1,%2,%3};"
        : "+f"(c[0]), "+f"(c[1]), "+f"(c[2]), "+f"(c[3])
        : "r"(a[0]), "r"(a[1]), "r"(a[2]), "r"(a[3]), "r"(b0), "r"(b1));
}

// SW128 swizzled address inside a ROWS x 128-byte tile.
DI uint32_t tile_addr(uint32_t base, int row, int chunk) {
    return base + row * 128 + (((chunk) ^ (row & 7)) << 4);
}

// Load a ROWS x 64-fp16 (128B/row) tile into SW128-swizzled SMEM via cp.async.
template <int NT, int ROWS>
DI void load_tile(uint32_t sdst, const __half* g, int row0, int col0, int ldk, int tid) {
#pragma unroll
    for (int i = 0; i < ROWS * 8 / NT; ++i) {
        int idx = tid + i * NT;
        int r = idx >> 3, c = idx & 7;
        uint32_t off = (uint32_t)(r * 128) + (uint32_t)(((c ^ (r & 7)) << 4));
        cp16(sdst + off, g + (size_t)(row0 + r) * ldk + col0 + c * 8);
    }
}

DI uint32_t pack2(float a, float b) {
    __half2 h = __floats2half2_rn(a, b);
    return reinterpret_cast<uint32_t&>(h);
}

DI __half2 u2h(uint32_t u) { return reinterpret_cast<__half2&>(u); }
DI uint32_t h2u(__half2 h) { return reinterpret_cast<uint32_t&>(h); }

// ---------------- SMEM layout ----------------
constexpr int STAGE  = 32768;
constexpr int NSTG   = 3;
constexpr int SPAR   = NSTG * STAGE;          // 98304
constexpr int SMEM_TOTAL = SPAR + 2048;       // 100352 -> 2 CTAs/SM

constexpr int NG1 = (DFF / 64) * (NTOK / 128);       // 2048 gemm1 tiles
constexpr int NG2 = (DMODEL / 128) * (NTOK / 128);   // 256 gemm2 tiles
constexpr int FPM = DFF / 64;                        // 64 f-tiles per m-block
constexpr int NW2 = 256;                             // producers that convert W2

// =====================================================================
// Kernel 0: fp32 -> fp16 conversion of x, W1a, W1b (W2 deferred into the
// fused kernel). Zeroes gating counters for strict per-replay gating.
// =====================================================================
__global__ void __launch_bounds__(256) convert_kernel(
    const float4* __restrict__ x, const float4* __restrict__ w1a,
    const float4* __restrict__ w1b)
{
    if (blockIdx.x == 0 && threadIdx.x <= NTOK / 128) {
        if (threadIdx.x < NTOK / 128) g_cnt[threadIdx.x] = 0;
        else g_w2done = 0;
    }
    int i = blockIdx.x * 256 + threadIdx.x;   // 4096*256 = 2^20 float4s per array
    float4 v;
    v = x[i];   ((uint2*)g_xh)[i]   = make_uint2(pack2(v.x, v.y), pack2(v.z, v.w));
    v = w1a[i]; ((uint2*)g_w1ah)[i] = make_uint2(pack2(v.x, v.y), pack2(v.z, v.w));
    v = w1b[i]; ((uint2*)g_w1bh)[i] = make_uint2(pack2(v.x, v.y), pack2(v.z, v.w));
}

// =====================================================================
// Fused kernel, 512 threads/CTA @ occupancy 2 (32 warps/SM experiment):
//   bids [0,2048)    : gemm1+InnerNet producers (128x64 tile, 4x4 warp grid,
//                      32x16 warp tiles). bids [0,256) convert a W2 slice
//                      after their epilogue.
//   bids [2048,2304) : gemm2 consumers (128x128 tile, 4x4 warp grid, 32x32
//                      warp tiles), gated on g_cnt[mi] + g_w2done.
// =====================================================================
__global__ void __launch_bounds__(512, 2) fused_kernel(
    const float4* __restrict__ w2f,
    const float* __restrict__ b1a, const float* __restrict__ b1b,
    const float* __restrict__ wi1, const float* __restrict__ bi1,
    const float* __restrict__ wi2, const float* __restrict__ bi2,
    const float* __restrict__ b2,  float* __restrict__ out)
{
    extern __shared__ char smem[];
    uint32_t sb = s2u(smem);
    int tid = threadIdx.x, lane = tid & 31, wid = tid >> 5;
    int bid = blockIdx.x;
    const int lr = lane & 15, lc = lane >> 4;
    const int g = lane >> 2, tg = lane & 3;

    if (bid < NG1) {
        // ================= GEMM1 + InnerNet (producer) =================
        int mi = bid >> 6;               // m-block (completes in order)
        int fi = bid & (FPM - 1);
        int f0 = fi * 64, m0 = mi * 128;
        int wm = wid & 3, wn = wid >> 2; // 4x4 warp grid, 32x16 warp tiles

        float*    sp  = (float*)(smem + SPAR);
        uint32_t* phu = (uint32_t*)(smem + SPAR + 512);
        if (tid < 64) { sp[tid] = b1a[f0 + tid]; sp[64 + tid] = b1b[f0 + tid]; }
        else if (tid < 96) {
            int h = tid - 64;
            phu[h * 4 + 0] = pack2(wi1[2 * h],     wi1[2 * h]);
            phu[h * 4 + 1] = pack2(wi1[2 * h + 1], wi1[2 * h + 1]);
            phu[h * 4 + 2] = pack2(bi1[h],         bi1[h]);
            phu[h * 4 + 3] = pack2(wi2[h],         wi2[h]);
        } else if (tid == 96) {
            phu[128] = pack2(bi2[0], bi2[0]);
        }

#pragma unroll
        for (int s = 0; s < 2; ++s) {
            uint32_t st = sb + s * STAGE;
            int col = s * 64;
            load_tile<512, 128>(st,         g_xh,   m0, col, DMODEL, tid);
            load_tile<512, 64 >(st + 16384, g_w1ah, f0, col, DMODEL, tid);
            load_tile<512, 64 >(st + 24576, g_w1bh, f0, col, DMODEL, tid);
            CP_COMMIT();
        }

        float acca[2][2][4], accb[2][2][4];
#pragma unroll
        for (int i = 0; i < 2; ++i)
#pragma unroll
            for (int j = 0; j < 2; ++j)
#pragma unroll
                for (int e = 0; e < 4; ++e) { acca[i][j][e] = 0.f; accb[i][j][e] = 0.f; }

        constexpr int NCH = DMODEL / 64;
        for (int c = 0; c < NCH; ++c) {
            CP_WAIT_1();
            __syncthreads();
            if (c + 2 < NCH) {
                uint32_t st = sb + ((c + 2) % 3) * STAGE;
                int col = (c + 2) * 64;
                load_tile<512, 128>(st,         g_xh,   m0, col, DMODEL, tid);
                load_tile<512, 64 >(st + 16384, g_w1ah, f0, col, DMODEL, tid);
                load_tile<512, 64 >(st + 24576, g_w1bh, f0, col, DMODEL, tid);
            }
            CP_COMMIT();

            uint32_t ab  = sb + (c % 3) * STAGE;
            uint32_t bab = ab + 16384;
            uint32_t bbb = ab + 24576;
#pragma unroll
            for (int ks = 0; ks < 4; ++ks) {
                uint32_t afr[2][4], bfa[4], bfb[4];
#pragma unroll
                for (int i = 0; i < 2; ++i)
                    ldsm4(afr[i], tile_addr(ab, wm * 32 + i * 16 + lr, ks * 2 + lc));
                ldsm4(bfa, tile_addr(bab, wn * 16 + lr, ks * 2 + lc));
                ldsm4(bfb, tile_addr(bbb, wn * 16 + lr, ks * 2 + lc));
#pragma unroll
                for (int i = 0; i < 2; ++i)
#pragma unroll
                    for (int j = 0; j < 2; ++j) {
                        mma16816(acca[i][j], afr[i], bfa[j], bfa[j + 2]);
                        mma16816(accb[i][j], afr[i], bfb[j], bfb[j + 2]);
                    }
            }
        }

        // ---- epilogue: bias + InnerNet in packed fp16, write fp16 act ----
        const __half2 BI2 = u2h(phu[128]);
        const __half2 Z2  = __floats2half2_rn(0.f, 0.f);
#pragma unroll
        for (int i = 0; i < 2; ++i) {
            __half2 A2[4], B2[4], acc0[4], acc1[4];
#pragma unroll
            for (int j = 0; j < 2; ++j) {
                int cb = wn * 16 + j * 8 + tg * 2;
                float ba0 = sp[cb], ba1 = sp[cb + 1];
                float bb0 = sp[64 + cb], bb1 = sp[64 + cb + 1];
                A2[j * 2]     = __floats2half2_rn(acca[i][j][0] + ba0, acca[i][j][1] + ba1);
                A2[j * 2 + 1] = __floats2half2_rn(acca[i][j][2] + ba0, acca[i][j][3] + ba1);
                B2[j * 2]     = __floats2half2_rn(accb[i][j][0] + bb0, accb[i][j][1] + bb1);
                B2[j * 2 + 1] = __floats2half2_rn(accb[i][j][2] + bb0, accb[i][j][3] + bb1);
                acc0[j * 2] = Z2; acc0[j * 2 + 1] = Z2;
                acc1[j * 2] = Z2; acc1[j * 2 + 1] = Z2;
            }
#pragma unroll 1
            for (int hh = 0; hh < HH / 2; ++hh) {
                __half2 W0e = u2h(phu[hh * 8 + 0]), W1e = u2h(phu[hh * 8 + 1]);
                __half2 CBe = u2h(phu[hh * 8 + 2]), VHe = u2h(phu[hh * 8 + 3]);
                __half2 W0o = u2h(phu[hh * 8 + 4]), W1o = u2h(phu[hh * 8 + 5]);
                __half2 CBo = u2h(phu[hh * 8 + 6]), VHo = u2h(phu[hh * 8 + 7]);
#pragma unroll
                for (int p = 0; p < 4; ++p) {
                    __half2 t0 = __hfma2_relu(A2[p], W0e, __hfma2(B2[p], W1e, CBe));
                    acc0[p] = __hfma2(t0, VHe, acc0[p]);
                    __half2 t1 = __hfma2_relu(A2[p], W0o, __hfma2(B2[p], W1o, CBo));
                    acc1[p] = __hfma2(t1, VHo, acc1[p]);
                }
            }
            int rowg = m0 + wm * 32 + i * 16 + g;
#pragma unroll
            for (int j = 0; j < 2; ++j) {
                int col = f0 + wn * 16 + j * 8 + tg * 2;
                __half2 s0 = __hadd2(__hadd2(acc0[j * 2],     acc1[j * 2]),     BI2);
                __half2 s1 = __hadd2(__hadd2(acc0[j * 2 + 1], acc1[j * 2 + 1]), BI2);
                *(uint32_t*)&g_act[(size_t)rowg * DFF + col]       = h2u(s0);
                *(uint32_t*)&g_act[(size_t)(rowg + 8) * DFF + col] = h2u(s1);
            }
        }

        // signal: this f-tile of m-block mi is done
        __syncthreads();
        if (tid == 0) {
            __threadfence();
            atomicAdd(&g_cnt[mi], 1);
        }

        // ---- W2 conversion tail (producers 0..255, end of wave 1) ----
        if (bid < NW2) {
            int base = bid * 4096;   // 2^20 float4 units / 256 CTAs
#pragma unroll 2
            for (int it = tid; it < 4096; it += 512) {
                int idx = base + it;
                float4 v = w2f[idx];
                ((uint2*)g_w2h)[idx] = make_uint2(pack2(v.x, v.y), pack2(v.z, v.w));
            }
            __syncthreads();
            if (tid == 0) { __threadfence(); atomicAdd(&g_w2done, 1); }
        }
    } else {
        // ================= GEMM2 (consumer) =================
        int t = bid - NG1;
        int mi = t >> 3, ni = t & 7;
        int m0 = mi * 128, n0 = ni * 128;
        int wm = wid >> 2, wn = wid & 3;  // 4x4 warp grid, 32x32 warp tiles

        float* sp = (float*)(smem + SPAR);
        if (tid < 128) sp[tid] = b2[n0 + tid];

        if (tid == 0) {
            while (atomicAdd(&g_w2done, 0) < NW2) __nanosleep(256);
            while (atomicAdd(&g_cnt[mi], 0) < FPM) __nanosleep(256);
            __threadfence();
        }
        __syncthreads();

#pragma unroll
        for (int s = 0; s < 2; ++s) {
            uint32_t st = sb + s * STAGE;
            load_tile<512, 128>(st,         g_act, m0, s * 64, DFF, tid);
            load_tile<512, 128>(st + 16384, g_w2h, n0, s * 64, DFF, tid);
            CP_COMMIT();
        }

        float acc[2][4][4];
#pragma unroll
        for (int i = 0; i < 2; ++i)
#pragma unroll
            for (int j = 0; j < 4; ++j)
#pragma unroll
                for (int e = 0; e < 4; ++e) acc[i][j][e] = 0.f;

        constexpr int NCH = DFF / 64;
        for (int c = 0; c < NCH; ++c) {
            CP_WAIT_1();
            __syncthreads();
            if (c + 2 < NCH) {
                uint32_t st = sb + ((c + 2) % 3) * STAGE;
                int col = (c + 2) * 64;
                load_tile<512, 128>(st,         g_act, m0, col, DFF, tid);
                load_tile<512, 128>(st + 16384, g_w2h, n0, col, DFF, tid);
            }
            CP_COMMIT();

            uint32_t ab = sb + (c % 3) * STAGE;
            uint32_t bb = ab + 16384;
#pragma unroll
            for (int ks = 0; ks < 4; ++ks) {
                uint32_t afr[2][4], bf[2][4];
#pragma unroll
                for (int i = 0; i < 2; ++i)
                    ldsm4(afr[i], tile_addr(ab, wm * 32 + i * 16 + lr, ks * 2 + lc));
#pragma unroll
                for (int q = 0; q < 2; ++q)
                    ldsm4(bf[q], tile_addr(bb, wn * 32 + q * 16 + lr, ks * 2 + lc));
#pragma unroll
                for (int i = 0; i < 2; ++i)
#pragma unroll
                    for (int j = 0; j < 4; ++j) {
                        int q = j >> 1, s = j & 1;
                        mma16816(acc[i][j], afr[i], bf[q][s], bf[q][s + 2]);
                    }
            }
        }

#pragma unroll
        for (int i = 0; i < 2; ++i) {
            int rowg = m0 + wm * 32 + i * 16 + g;
#pragma unroll
            for (int j = 0; j < 4; ++j) {
                int cb = wn * 32 + j * 8 + tg * 2;
                float2 v0 = make_float2(acc[i][j][0] + sp[cb], acc[i][j][1] + sp[cb + 1]);
                float2 v1 = make_float2(acc[i][j][2] + sp[cb], acc[i][j][3] + sp[cb + 1]);
                *(float2*)&out[(size_t)rowg * DMODEL + n0 + cb]       = v0;
                *(float2*)&out[(size_t)(rowg + 8) * DMODEL + n0 + cb] = v1;
            }
        }
    }
}

// =====================================================================
// launch
// =====================================================================
extern "C" void kernel_launch(void* const* d_in, const int* in_sizes, int n_in,
                              void* d_out, int out_size)
{
    const float* x   = (const float*)d_in[0];
    const float* W1a = (const float*)d_in[1];
    const float* b1a = (const float*)d_in[2];
    const float* W1b = (const float*)d_in[3];
    const float* b1b = (const float*)d_in[4];
    const float* Wi1 = (const float*)d_in[5];
    const float* bi1 = (const float*)d_in[6];
    const float* Wi2 = (const float*)d_in[7];
    const float* bi2 = (const float*)d_in[8];
    const float* W2  = (const float*)d_in[9];
    const float* b2  = (const float*)d_in[10];
    float* out = (float*)d_out;

    cudaFuncSetAttribute(fused_kernel, cudaFuncAttributeMaxDynamicSharedMemorySize, SMEM_TOTAL);

    convert_kernel<<<4096, 256>>>((const float4*)x, (const float4*)W1a, (const float4*)W1b);
    fused_kernel<<<NG1 + NG2, 512, SMEM_TOTAL>>>(
        (const float4*)W2, b1a, b1b, Wi1, bi1, Wi2, bi2, b2, out);
}

// round 15
// speedup vs baseline: 1.0665x; 1.0665x over previous
#include <cuda_runtime.h>
#include <cuda_fp16.h>
#include <cstdint>

#define DI __device__ __forceinline__

// ---------------- problem constants (fixed shapes) ----------------
constexpr int NTOK   = 4096;   // B*S = 2*2048
constexpr int DMODEL = 1024;
constexpr int DFF    = 4096;
constexpr int HH     = 32;

// ---------------- scratch (device globals; no allocs allowed) ----------------
__device__ __align__(16) __half g_xh  [NTOK * DMODEL];      // 8 MB
__device__ __align__(16) __half g_w1ah[DFF  * DMODEL];      // 8 MB
__device__ __align__(16) __half g_w1bh[DFF  * DMODEL];      // 8 MB
__device__ __align__(16) __half g_w2h [DMODEL * DFF];       // 8 MB
__device__ __align__(16) __half g_act [(size_t)NTOK * DFF]; // 32 MB
__device__ int g_cnt[NTOK / 128];    // per-m-block gemm1 completion (zeroed each launch)
__device__ int g_w2done;             // W2 conversion progress     (zeroed each launch)

// ---------------- PTX helpers ----------------
DI uint32_t s2u(const void* p) {
    uint32_t a;
    asm("{ .reg .u64 t; cvta.to.shared.u64 t, %1; cvt.u32.u64 %0, t; }"
        : "=r"(a) : "l"(p));
    return a;
}

#define CP_COMMIT() asm volatile("cp.async.commit_group;" ::: "memory")
#define CP_WAIT_1() asm volatile("cp.async.wait_group 1;" ::: "memory")

DI void cp16(uint32_t sdst, const void* gsrc) {
    asm volatile("cp.async.cg.shared.global [%0], [%1], 16;"
                 :: "r"(sdst), "l"(__cvta_generic_to_global(gsrc)) : "memory");
}

DI void ldsm4(uint32_t r[4], uint32_t addr) {
    asm volatile("ldmatrix.sync.aligned.m8n8.x4.shared.b16 {%0,%1,%2,%3}, [%4];"
                 : "=r"(r[0]), "=r"(r[1]), "=r"(r[2]), "=r"(r[3]) : "r"(addr));
}

DI void mma16816(float c[4], const uint32_t a[4], uint32_t b0, uint32_t b1) {
    asm volatile(
        "mma.sync.aligned.m16n8k16.row.col.f32.f16.f16.f32 "
        "{%0,%1,%2,%3}, {%4,%5,%6,%7}, {%8,%9}, {%0,%1,%2,%3};"
        : "+f"(c[0]), "+f"(c[1]), "+f"(c[2]), "+f"(c[3])
        : "r"(a[0]), "r"(a[1]), "r"(a[2]), "r"(a[3]), "r"(b0), "r"(b1));
}

// SW128 swizzled address inside a ROWS x 128-byte tile.
DI uint32_t tile_addr(uint32_t base, int row, int chunk) {
    return base + row * 128 + (((chunk) ^ (row & 7)) << 4);
}

// Load a ROWS x 64-fp16 (128B/row) tile into SW128-swizzled SMEM via cp.async.
template <int NT, int ROWS>
DI void load_tile(uint32_t sdst, const __half* g, int row0, int col0, int ldk, int tid) {
#pragma unroll
    for (int i = 0; i < ROWS * 8 / NT; ++i) {
        int idx = tid + i * NT;
        int r = idx >> 3, c = idx & 7;
        uint32_t off = (uint32_t)(r * 128) + (uint32_t)(((c ^ (r & 7)) << 4));
        cp16(sdst + off, g + (size_t)(row0 + r) * ldk + col0 + c * 8);
    }
}

DI uint32_t pack2(float a, float b) {
    __half2 h = __floats2half2_rn(a, b);
    return reinterpret_cast<uint32_t&>(h);
}

DI __half2 u2h(uint32_t u) { return reinterpret_cast<__half2&>(u); }
DI uint32_t h2u(__half2 h) { return reinterpret_cast<uint32_t&>(h); }

// ---------------- SMEM layout ----------------
constexpr int STAGE  = 32768;
constexpr int NSTG   = 3;
constexpr int SPAR   = NSTG * STAGE;          // 98304
constexpr int SMEM_TOTAL = SPAR + 2048;       // 100352 -> 2 CTAs/SM

constexpr int NG1 = (DFF / 64) * (NTOK / 128);       // 2048 gemm1 tiles
constexpr int NG2 = (DMODEL / 128) * (NTOK / 128);   // 256 gemm2 tiles
constexpr int FPM = DFF / 64;                        // 64 f-tiles per m-block
constexpr int NW2 = 256;                             // producers that convert W2

// =====================================================================
// Kernel 0: fp32 -> fp16 conversion of x, W1a, W1b ONLY (W2 is converted
// inside the fused kernel, hidden under gemm1). Zeroes the gating counters
// so every graph replay gates strictly.
// =====================================================================
__global__ void __launch_bounds__(256) convert_kernel(
    const float4* __restrict__ x, const float4* __restrict__ w1a,
    const float4* __restrict__ w1b)
{
    if (blockIdx.x == 0 && threadIdx.x <= NTOK / 128) {
        if (threadIdx.x < NTOK / 128) g_cnt[threadIdx.x] = 0;
        else g_w2done = 0;
    }
    int i = blockIdx.x * 256 + threadIdx.x;   // 4096*256 = 2^20 float4s per array
    float4 v;
    v = x[i];   ((uint2*)g_xh)[i]   = make_uint2(pack2(v.x, v.y), pack2(v.z, v.w));
    v = w1a[i]; ((uint2*)g_w1ah)[i] = make_uint2(pack2(v.x, v.y), pack2(v.z, v.w));
    v = w1b[i]; ((uint2*)g_w1bh)[i] = make_uint2(pack2(v.x, v.y), pack2(v.z, v.w));
}

// =====================================================================
// Fused kernel: bids [0,2048) run gemm1+InnerNet tiles (f-major within
// m-block so m-blocks complete in order); bids [0,256) additionally convert
// a 64KB slice of W2 AFTER their epilogue (end of wave 1, hidden under
// later gemm1 waves). Bids [2048,2304) run gemm2 tiles gated on their
// m-block counter + W2 completion. HW dispatches in bid order -> all
// producers start before any consumer -> no deadlock.
// =====================================================================
__global__ void __launch_bounds__(256, 2) fused_kernel(
    const float4* __restrict__ w2f,
    const float* __restrict__ b1a, const float* __restrict__ b1b,
    const float* __restrict__ wi1, const float* __restrict__ bi1,
    const float* __restrict__ wi2, const float* __restrict__ bi2,
    const float* __restrict__ b2,  float* __restrict__ out)
{
    extern __shared__ char smem[];
    uint32_t sb = s2u(smem);
    int tid = threadIdx.x, lane = tid & 31, wid = tid >> 5;
    int bid = blockIdx.x;
    const int lr = lane & 15, lc = lane >> 4;
    const int g = lane >> 2, tg = lane & 3;

    if (bid < NG1) {
        // ================= GEMM1 + InnerNet (producer) =================
        int mi = bid >> 6;               // m-block (completes in order)
        int fi = bid & (FPM - 1);
        int f0 = fi * 64, m0 = mi * 128;
        int wm = wid & 3, wn = wid >> 2; // 4x2 warp grid, 32x32 tiles

        float*    sp  = (float*)(smem + SPAR);
        uint32_t* phu = (uint32_t*)(smem + SPAR + 512);
        if (tid < 64) { sp[tid] = b1a[f0 + tid]; sp[64 + tid] = b1b[f0 + tid]; }
        else if (tid < 96) {
            int h = tid - 64;
            phu[h * 4 + 0] = pack2(wi1[2 * h],     wi1[2 * h]);
            phu[h * 4 + 1] = pack2(wi1[2 * h + 1], wi1[2 * h + 1]);
            phu[h * 4 + 2] = pack2(bi1[h],         bi1[h]);
            phu[h * 4 + 3] = pack2(wi2[h],         wi2[h]);
        } else if (tid == 96) {
            phu[128] = pack2(bi2[0], bi2[0]);
        }

#pragma unroll
        for (int s = 0; s < 2; ++s) {
            uint32_t st = sb + s * STAGE;
            int col = s * 64;
            load_tile<256, 128>(st,         g_xh,   m0, col, DMODEL, tid);
            load_tile<256, 64 >(st + 16384, g_w1ah, f0, col, DMODEL, tid);
            load_tile<256, 64 >(st + 24576, g_w1bh, f0, col, DMODEL, tid);
            CP_COMMIT();
        }

        float acca[2][4][4], accb[2][4][4];
#pragma unroll
        for (int i = 0; i < 2; ++i)
#pragma unroll
            for (int j = 0; j < 4; ++j)
#pragma unroll
                for (int e = 0; e < 4; ++e) { acca[i][j][e] = 0.f; accb[i][j][e] = 0.f; }

        constexpr int NCH = DMODEL / 64;
        for (int c = 0; c < NCH; ++c) {
            CP_WAIT_1();
            __syncthreads();
            if (c + 2 < NCH) {
                uint32_t st = sb + ((c + 2) % 3) * STAGE;
                int col = (c + 2) * 64;
                load_tile<256, 128>(st,         g_xh,   m0, col, DMODEL, tid);
                load_tile<256, 64 >(st + 16384, g_w1ah, f0, col, DMODEL, tid);
                load_tile<256, 64 >(st + 24576, g_w1bh, f0, col, DMODEL, tid);
            }
            CP_COMMIT();

            uint32_t ab  = sb + (c % 3) * STAGE;
            uint32_t bab = ab + 16384;
            uint32_t bbb = ab + 24576;
#pragma unroll
            for (int ks = 0; ks < 4; ++ks) {
                uint32_t afr[2][4], bfa[2][4], bfb[2][4];
#pragma unroll
                for (int i = 0; i < 2; ++i)
                    ldsm4(afr[i], tile_addr(ab, wm * 32 + i * 16 + lr, ks * 2 + lc));
#pragma unroll
                for (int q = 0; q < 2; ++q) {
                    ldsm4(bfa[q], tile_addr(bab, wn * 32 + q * 16 + lr, ks * 2 + lc));
                    ldsm4(bfb[q], tile_addr(bbb, wn * 32 + q * 16 + lr, ks * 2 + lc));
                }
#pragma unroll
                for (int i = 0; i < 2; ++i)
#pragma unroll
                    for (int j = 0; j < 4; ++j) {
                        int q = j >> 1, s = j & 1;
                        mma16816(acca[i][j], afr[i], bfa[q][s], bfa[q][s + 2]);
                        mma16816(accb[i][j], afr[i], bfb[q][s], bfb[q][s + 2]);
                    }
            }
        }

        // ---- epilogue: bias + InnerNet in packed fp16, write fp16 act ----
        const __half2 BI2 = u2h(phu[128]);
        const __half2 Z2  = __floats2half2_rn(0.f, 0.f);
#pragma unroll
        for (int i = 0; i < 2; ++i) {
            __half2 A2[8], B2[8], acc0[8], acc1[8];
#pragma unroll
            for (int j = 0; j < 4; ++j) {
                int cb = wn * 32 + j * 8 + tg * 2;
                float ba0 = sp[cb], ba1 = sp[cb + 1];
                float bb0 = sp[64 + cb], bb1 = sp[64 + cb + 1];
                A2[j * 2]     = __floats2half2_rn(acca[i][j][0] + ba0, acca[i][j][1] + ba1);
                A2[j * 2 + 1] = __floats2half2_rn(acca[i][j][2] + ba0, acca[i][j][3] + ba1);
                B2[j * 2]     = __floats2half2_rn(accb[i][j][0] + bb0, accb[i][j][1] + bb1);
                B2[j * 2 + 1] = __floats2half2_rn(accb[i][j][2] + bb0, accb[i][j][3] + bb1);
                acc0[j * 2] = Z2; acc0[j * 2 + 1] = Z2;
                acc1[j * 2] = Z2; acc1[j * 2 + 1] = Z2;
            }
#pragma unroll 1
            for (int hh = 0; hh < HH / 2; ++hh) {
                __half2 W0e = u2h(phu[hh * 8 + 0]), W1e = u2h(phu[hh * 8 + 1]);
                __half2 CBe = u2h(phu[hh * 8 + 2]), VHe = u2h(phu[hh * 8 + 3]);
                __half2 W0o = u2h(phu[hh * 8 + 4]), W1o = u2h(phu[hh * 8 + 5]);
                __half2 CBo = u2h(phu[hh * 8 + 6]), VHo = u2h(phu[hh * 8 + 7]);
#pragma unroll
                for (int p = 0; p < 8; ++p) {
                    __half2 t0 = __hfma2_relu(A2[p], W0e, __hfma2(B2[p], W1e, CBe));
                    acc0[p] = __hfma2(t0, VHe, acc0[p]);
                    __half2 t1 = __hfma2_relu(A2[p], W0o, __hfma2(B2[p], W1o, CBo));
                    acc1[p] = __hfma2(t1, VHo, acc1[p]);
                }
            }
            int rowg = m0 + wm * 32 + i * 16 + g;
#pragma unroll
            for (int j = 0; j < 4; ++j) {
                int col = f0 + wn * 32 + j * 8 + tg * 2;
                __half2 s0 = __hadd2(__hadd2(acc0[j * 2],     acc1[j * 2]),     BI2);
                __half2 s1 = __hadd2(__hadd2(acc0[j * 2 + 1], acc1[j * 2 + 1]), BI2);
                *(uint32_t*)&g_act[(size_t)rowg * DFF + col]       = h2u(s0);
                *(uint32_t*)&g_act[(size_t)(rowg + 8) * DFF + col] = h2u(s1);
            }
        }

        // signal: this f-tile of m-block mi is done
        __syncthreads();
        if (tid == 0) {
            __threadfence();
            atomicAdd(&g_cnt[mi], 1);
        }

        // ---- W2 conversion tail (producers 0..255, end of wave 1) ----
        if (bid < NW2) {
            int base = bid * 4096;   // 2^20 float4 units / 256 CTAs
#pragma unroll 4
            for (int it = tid; it < 4096; it += 256) {
                int idx = base + it;
                float4 v = w2f[idx];
                ((uint2*)g_w2h)[idx] = make_uint2(pack2(v.x, v.y), pack2(v.z, v.w));
            }
            __syncthreads();
            if (tid == 0) { __threadfence(); atomicAdd(&g_w2done, 1); }
        }
    } else {
        // ================= GEMM2 (consumer) =================
        int t = bid - NG1;
        int mi = t >> 3, ni = t & 7;
        int m0 = mi * 128, n0 = ni * 128;
        int wm = wid >> 2, wn = wid & 3;  // 2x4 warp grid, 64x32 tiles

        float* sp = (float*)(smem + SPAR);
        if (tid < 128) sp[tid] = b2[n0 + tid];

        // gate: W2 converted + all 64 producer tiles of this m-block done
        if (tid == 0) {
            while (atomicAdd(&g_w2done, 0) < NW2) __nanosleep(256);
            while (atomicAdd(&g_cnt[mi], 0) < FPM) __nanosleep(256);
            __threadfence();
        }
        __syncthreads();

#pragma unroll
        for (int s = 0; s < 2; ++s) {
            uint32_t st = sb + s * STAGE;
            load_tile<256, 128>(st,         g_act, m0, s * 64, DFF, tid);
            load_tile<256, 128>(st + 16384, g_w2h, n0, s * 64, DFF, tid);
            CP_COMMIT();
        }

        float acc[4][4][4];
#pragma unroll
        for (int i = 0; i < 4; ++i)
#pragma unroll
            for (int j = 0; j < 4; ++j)
#pragma unroll
                for (int e = 0; e < 4; ++e) acc[i][j][e] = 0.f;

        constexpr int NCH = DFF / 64;
        for (int c = 0; c < NCH; ++c) {
            CP_WAIT_1();
            __syncthreads();
            if (c + 2 < NCH) {
                uint32_t st = sb + ((c + 2) % 3) * STAGE;
                int col = (c + 2) * 64;
                load_tile<256, 128>(st,         g_act, m0, col, DFF, tid);
                load_tile<256, 128>(st + 16384, g_w2h, n0, col, DFF, tid);
            }
            CP_COMMIT();

            uint32_t ab = sb + (c % 3) * STAGE;
            uint32_t bb = ab + 16384;
#pragma unroll
            for (int ks = 0; ks < 4; ++ks) {
                uint32_t afr[4][4], bf[2][4];
#pragma unroll
                for (int i = 0; i < 4; ++i)
                    ldsm4(afr[i], tile_addr(ab, wm * 64 + i * 16 + lr, ks * 2 + lc));
#pragma unroll
                for (int q = 0; q < 2; ++q)
                    ldsm4(bf[q], tile_addr(bb, wn * 32 + q * 16 + lr, ks * 2 + lc));
#pragma unroll
                for (int i = 0; i < 4; ++i)
#pragma unroll
                    for (int j = 0; j < 4; ++j) {
                        int q = j >> 1, s = j & 1;
                        mma16816(acc[i][j], afr[i], bf[q][s], bf[q][s + 2]);
                    }
            }
        }

#pragma unroll
        for (int i = 0; i < 4; ++i) {
            int rowg = m0 + wm * 64 + i * 16 + g;
#pragma unroll
            for (int j = 0; j < 4; ++j) {
                int cb = wn * 32 + j * 8 + tg * 2;
                float2 v0 = make_float2(acc[i][j][0] + sp[cb], acc[i][j][1] + sp[cb + 1]);
                float2 v1 = make_float2(acc[i][j][2] + sp[cb], acc[i][j][3] + sp[cb + 1]);
                *(float2*)&out[(size_t)rowg * DMODEL + n0 + cb]       = v0;
                *(float2*)&out[(size_t)(rowg + 8) * DMODEL + n0 + cb] = v1;
            }
        }
    }
}

// =====================================================================
// launch
// =====================================================================
extern "C" void kernel_launch(void* const* d_in, const int* in_sizes, int n_in,
                              void* d_out, int out_size)
{
    const float* x   = (const float*)d_in[0];
    const float* W1a = (const float*)d_in[1];
    const float* b1a = (const float*)d_in[2];
    const float* W1b = (const float*)d_in[3];
    const float* b1b = (const float*)d_in[4];
    const float* Wi1 = (const float*)d_in[5];
    const float* bi1 = (const float*)d_in[6];
    const float* Wi2 = (const float*)d_in[7];
    const float* bi2 = (const float*)d_in[8];
    const float* W2  = (const float*)d_in[9];
    const float* b2  = (const float*)d_in[10];
    float* out = (float*)d_out;

    cudaFuncSetAttribute(fused_kernel, cudaFuncAttributeMaxDynamicSharedMemorySize, SMEM_TOTAL);

    convert_kernel<<<4096, 256>>>((const float4*)x, (const float4*)W1a, (const float4*)W1b);
    fused_kernel<<<NG1 + NG2, 256, SMEM_TOTAL>>>(
        (const float4*)W2, b1a, b1b, Wi1, bi1, Wi2, bi2, b2, out);
}